// round 10
// baseline (speedup 1.0000x reference)
#include <cuda_runtime.h>
#include <cstdint>

#define HID 64
#define EXT 32
#define TN 64
#define TM 128          // edges per tile
#define MAX_NODES 50000

// ---------------------------------------------------------------------------
// Globals
// ---------------------------------------------------------------------------
__device__ float g_P[MAX_NODES * HID];        // h @ (W1a@W2a)
__device__ float g_Q[MAX_NODES * HID];        // h @ (W1c@W2a) + b12 (bias baked in)
__device__ float g_W12[HID * HID];            // W1b @ W2a (fp32)
__device__ float g_Wa2[HID * HID];
__device__ float g_Wc2[HID * HID];
__device__ float g_b12[HID];                  // b1 @ W2a + b2
// Split bf16 weights, packed as bf16x2 per k-pair: g_Bp[kp][n], kp = k/2.
// kp [0:32)=W12_hi [32:64)=W12_lo [64:80)=W2b_hi [80:96)=W2b_lo
__device__ unsigned g_Bp[96 * 64];

typedef unsigned long long u64;

// Single extern shared declaration for all kernels
extern __shared__ __align__(16) unsigned char smraw[];

// ---------------------------------------------------------------------------
// Helpers
// ---------------------------------------------------------------------------
__device__ __forceinline__ uint32_t smem_u32(const void* p) {
    uint32_t a;
    asm("{ .reg .u64 t; cvta.to.shared.u64 t, %1; cvt.u32.u64 %0, t; }" : "=r"(a) : "l"(p));
    return a;
}
__device__ __forceinline__ u64 pk2(float x, float y) {
    u64 r; asm("mov.b64 %0,{%1,%2};" : "=l"(r) : "f"(x), "f"(y)); return r;
}
__device__ __forceinline__ float2 up2(u64 v) {
    float2 f; asm("mov.b64 {%0,%1},%2;" : "=f"(f.x), "=f"(f.y) : "l"(v)); return f;
}
__device__ __forceinline__ void ffma2(u64& d, u64 a, u64 b) {
    asm("fma.rn.f32x2 %0,%1,%2,%0;" : "+l"(d) : "l"(a), "l"(b));
}
// bf16 hi/lo split of two floats, packed as bf16x2 words (x0 -> low half)
__device__ __forceinline__ void split2(float x0, float x1, unsigned& hi, unsigned& lo) {
    unsigned h;
    asm("cvt.rn.bf16x2.f32 %0, %1, %2;" : "=r"(h) : "f"(x1), "f"(x0));
    float h0 = __uint_as_float(h << 16);
    float h1 = __uint_as_float(h & 0xFFFF0000u);
    float l0 = x0 - h0, l1 = x1 - h1;
    unsigned l;
    asm("cvt.rn.bf16x2.f32 %0, %1, %2;" : "=r"(l) : "f"(l1), "f"(l0));
    hi = h; lo = l;
}
__device__ __forceinline__ void mma16816(float* c, uint4 a, unsigned b0, unsigned b1) {
    asm volatile(
        "mma.sync.aligned.m16n8k16.row.col.f32.bf16.bf16.f32 "
        "{%0,%1,%2,%3},{%4,%5,%6,%7},{%8,%9},{%0,%1,%2,%3};"
        : "+f"(c[0]), "+f"(c[1]), "+f"(c[2]), "+f"(c[3])
        : "r"(a.x), "r"(a.y), "r"(a.z), "r"(a.w), "r"(b0), "r"(b1));
}
__device__ __forceinline__ void ldm4(uint4& a, unsigned addr) {
    asm volatile("ldmatrix.sync.aligned.m8n8.x4.shared.b16 {%0,%1,%2,%3}, [%4];"
        : "=r"(a.x), "=r"(a.y), "=r"(a.z), "=r"(a.w) : "r"(addr));
}

// A smem: 128 rows x 24 16B-units (384B/row), XOR-swizzled within 8-unit groups.
// Unit layout per row: kb 0..5 owns units [4kb..4kb+4): [hi_u0, hi_u1, lo_u0, lo_u1]
// (u0 = orig k 0-7 of the 16-block, u1 = k 8-15). kb 0-3 = e_h, kb 4-5 = ext.
__device__ __forceinline__ unsigned rowaddr(int r, int u) {
    int us = (u & ~7) | ((u ^ r) & 7);
    return (unsigned)(r * 384 + us * 16);
}

// ---------------------------------------------------------------------------
// Kernel 0a: fold W2a into W1 parts + bias.  grid 49 x 256
// ---------------------------------------------------------------------------
__global__ __launch_bounds__(256) void combo_kernel(
    const float* __restrict__ W1, const float* __restrict__ b1,
    const float* __restrict__ W2, const float* __restrict__ b2)
{
    __shared__ float W2s[HID * HID];
    __shared__ float rW[256];
    for (int i = threadIdx.x; i < HID * HID; i += 256) W2s[i] = W2[i];

    int b = blockIdx.x;
    if (b < 48) {
        int mat = b >> 4, rb = b & 15;
        rW[threadIdx.x] = W1[(size_t)mat * HID * HID + rb * 256 + threadIdx.x];
        __syncthreads();
        int lr = threadIdx.x >> 6, col = threadIdx.x & 63;
        float acc = 0.f;
        #pragma unroll 8
        for (int k = 0; k < HID; k++)
            acc = fmaf(rW[lr * HID + k], W2s[k * HID + col], acc);
        float* dstW = (mat == 0) ? g_Wa2 : (mat == 1) ? g_W12 : g_Wc2;
        dstW[(rb * 4 + lr) * HID + col] = acc;
    } else {
        __syncthreads();
        if (threadIdx.x < HID) {
            float acc = b2[threadIdx.x];
            #pragma unroll 8
            for (int k = 0; k < HID; k++)
                acc = fmaf(b1[k], W2s[k * HID + threadIdx.x], acc);
            g_b12[threadIdx.x] = acc;
        }
    }
}

// ---------------------------------------------------------------------------
// Kernel 0b: build split bf16x2 weight blob.  grid 12 x 256
// ---------------------------------------------------------------------------
__global__ __launch_bounds__(256) void build_B(const float* __restrict__ W2)
{
    int idx = blockIdx.x * 256 + threadIdx.x;
    if (idx < 48 * 64) {
        int kp = idx >> 6, n = idx & 63;
        float x0, x1;
        int hi_kp, lo_kp;
        if (kp < 32) {
            x0 = g_W12[(2 * kp) * HID + n];
            x1 = g_W12[(2 * kp + 1) * HID + n];
            hi_kp = kp; lo_kp = 32 + kp;
        } else {
            int ks = kp - 32;
            x0 = W2[(size_t)(HID + 2 * ks) * HID + n];
            x1 = W2[(size_t)(HID + 2 * ks + 1) * HID + n];
            hi_kp = 64 + ks; lo_kp = 80 + ks;
        }
        unsigned hi, lo;
        split2(x0, x1, hi, lo);
        g_Bp[hi_kp * 64 + n] = hi;
        g_Bp[lo_kp * 64 + n] = lo;
    }
}

// ---------------------------------------------------------------------------
// Kernel 1: per-node  P = h @ Wa2 ; Q = h @ Wc2 + b12   (FFMA2)
// ---------------------------------------------------------------------------
#define NODE_SMEM_BYTES ((4096 + 4096 + HID * TN) * 4)

__global__ __launch_bounds__(256) void node_pre(const float* __restrict__ h,
                                                int n_nodes)
{
    float* sm  = (float*)smraw;
    float* Wa  = sm;
    float* Wc  = Wa + 4096;
    float* hst = Wc + 4096;

    for (int i = threadIdx.x; i < HID * HID; i += 256) {
        Wa[i] = g_Wa2[i];
        Wc[i] = g_Wc2[i];
    }

    const int tx = threadIdx.x & 15;
    const int ty = threadIdx.x >> 4;
    const int j0 = tx * 4;
    const int r0 = ty * 4;
    const int ntiles = (n_nodes + TN - 1) / TN;

    float4 bv = *(const float4*)(g_b12 + j0);
    u64 qb0 = pk2(bv.x, bv.x), qb1 = pk2(bv.y, bv.y),
        qb2 = pk2(bv.z, bv.z), qb3 = pk2(bv.w, bv.w);

    for (int tile = blockIdx.x; tile < ntiles; tile += gridDim.x) {
        const int base = tile * TN;
        __syncthreads();
        for (int idx = threadIdx.x; idx < (HID / 4) * TN; idx += 256) {
            int cq = idx >> 6;
            int r  = idx & (TN - 1);
            int node = base + r;
            float4 v = make_float4(0.f, 0.f, 0.f, 0.f);
            if (node < n_nodes) v = *(const float4*)(h + (size_t)node * HID + cq * 4);
            hst[(cq * 4 + 0) * TN + r] = v.x;
            hst[(cq * 4 + 1) * TN + r] = v.y;
            hst[(cq * 4 + 2) * TN + r] = v.z;
            hst[(cq * 4 + 3) * TN + r] = v.w;
        }
        __syncthreads();

        u64 aP[4][2], aQ[4][2];
        #pragma unroll
        for (int j = 0; j < 4; j++) aP[j][0] = aP[j][1] = 0ULL;
        aQ[0][0] = aQ[0][1] = qb0;
        aQ[1][0] = aQ[1][1] = qb1;
        aQ[2][0] = aQ[2][1] = qb2;
        aQ[3][0] = aQ[3][1] = qb3;

        #pragma unroll 4
        for (int k = 0; k < HID; k++) {
            ulonglong2 sv = *(const ulonglong2*)(hst + k * TN + r0);
            float4 wa = *(const float4*)(Wa + k * HID + j0);
            float4 wc = *(const float4*)(Wc + k * HID + j0);
            u64 a0 = pk2(wa.x, wa.x), a1 = pk2(wa.y, wa.y),
                a2 = pk2(wa.z, wa.z), a3 = pk2(wa.w, wa.w);
            u64 c0 = pk2(wc.x, wc.x), c1 = pk2(wc.y, wc.y),
                c2 = pk2(wc.z, wc.z), c3 = pk2(wc.w, wc.w);
            ffma2(aP[0][0], a0, sv.x); ffma2(aP[0][1], a0, sv.y);
            ffma2(aP[1][0], a1, sv.x); ffma2(aP[1][1], a1, sv.y);
            ffma2(aP[2][0], a2, sv.x); ffma2(aP[2][1], a2, sv.y);
            ffma2(aP[3][0], a3, sv.x); ffma2(aP[3][1], a3, sv.y);
            ffma2(aQ[0][0], c0, sv.x); ffma2(aQ[0][1], c0, sv.y);
            ffma2(aQ[1][0], c1, sv.x); ffma2(aQ[1][1], c1, sv.y);
            ffma2(aQ[2][0], c2, sv.x); ffma2(aQ[2][1], c2, sv.y);
            ffma2(aQ[3][0], c3, sv.x); ffma2(aQ[3][1], c3, sv.y);
        }
        #pragma unroll
        for (int r = 0; r < 4; r++) {
            int node = base + r0 + r;
            if (node < n_nodes) {
                float4 p, q; float2 c;
                c = up2(aP[0][r >> 1]); p.x = (r & 1) ? c.y : c.x;
                c = up2(aP[1][r >> 1]); p.y = (r & 1) ? c.y : c.x;
                c = up2(aP[2][r >> 1]); p.z = (r & 1) ? c.y : c.x;
                c = up2(aP[3][r >> 1]); p.w = (r & 1) ? c.y : c.x;
                c = up2(aQ[0][r >> 1]); q.x = (r & 1) ? c.y : c.x;
                c = up2(aQ[1][r >> 1]); q.y = (r & 1) ? c.y : c.x;
                c = up2(aQ[2][r >> 1]); q.z = (r & 1) ? c.y : c.x;
                c = up2(aQ[3][r >> 1]); q.w = (r & 1) ? c.y : c.x;
                *(float4*)(g_P + (size_t)node * HID + j0) = p;
                *(float4*)(g_Q + (size_t)node * HID + j0) = q;
            }
        }
    }
}

// ---------------------------------------------------------------------------
// Kernel 2: per-edge via mma.sync + ldmatrix, hi/lo-interleaved K blocks.
//   kb 0..3 = e_h 16-col blocks, kb 4..5 = ext 16-col blocks.
//   Per kb: A_hi x W_hi, A_hi x W_lo (cross), A_lo x W_hi  -> 18 MMA / m-tile.
//   out = relu( sum + P[src] + Q[dst] )
// ---------------------------------------------------------------------------
#define A_BYTES (TM * 384)              // 49152
#define OFF_SRC A_BYTES
#define OFF_DST (OFF_SRC + TM * 4)
#define EDGE_SMEM_BYTES (OFF_DST + TM * 4)

__global__ __launch_bounds__(256) void edge_kernel(
    const float* __restrict__ e_h,
    const float* __restrict__ ext,
    const int* __restrict__ src,
    const int* __restrict__ dst,
    float* __restrict__ out,
    int n_edges)
{
    unsigned char* A = smraw;
    int* srcs = (int*)(smraw + OFF_SRC);
    int* dsts = (int*)(smraw + OFF_DST);
    const uint32_t smb = smem_u32(smraw);

    const int tid = threadIdx.x;
    const int w = tid >> 5, lane = tid & 31;
    const int n0 = w * 8;
    const int lr = lane >> 2;            // 0..7
    const int lc = lane & 3;             // 0..3
    // ldmatrix address lanes: rows (lane>>3 & 1)*8 + (lane&7), k-half = lane>>4
    const int rbase = ((lane >> 3) & 1) * 8 + (lane & 7);
    const int ubase = lane >> 4;

    // ---- B fragments (registers, live whole kernel); words shared across kt ----
    unsigned bh0[6], bh1[6], bl0[6], bl1[6];
    #pragma unroll
    for (int kb = 0; kb < 6; kb++) {
        int kph = (kb < 4) ? (kb * 8 + lc) : (64 + (kb - 4) * 8 + lc);
        int kpl = (kb < 4) ? (32 + kb * 8 + lc) : (80 + (kb - 4) * 8 + lc);
        bh0[kb] = g_Bp[kph * 64 + n0 + lr];
        bh1[kb] = g_Bp[(kph + 4) * 64 + n0 + lr];
        bl0[kb] = g_Bp[kpl * 64 + n0 + lr];
        bl1[kb] = g_Bp[(kpl + 4) * 64 + n0 + lr];
    }

    const int ntiles = (n_edges + TM - 1) / TM;

    for (int tile = blockIdx.x; tile < ntiles; tile += gridDim.x) {
        const int base = tile * TM;
        __syncthreads();   // previous tile fully consumed before A overwrite

        // ---- stage e_h: thread handles (row r, 8 cols c8..c8+7) -> 2 STS.128 ----
        for (int idx = tid; idx < TM * 8; idx += 256) {
            int r = idx >> 3, c8 = (idx & 7) << 3;
            int e = base + r;
            float4 v0, v1;
            if (e < n_edges) {
                v0 = *(const float4*)(e_h + (size_t)e * HID + c8);
                v1 = *(const float4*)(e_h + (size_t)e * HID + c8 + 4);
            } else {
                v0 = v1 = make_float4(0.f, 0.f, 0.f, 0.f);
            }
            unsigned h01, l01, h23, l23, h45, l45, h67, l67;
            split2(v0.x, v0.y, h01, l01);
            split2(v0.z, v0.w, h23, l23);
            split2(v1.x, v1.y, h45, l45);
            split2(v1.z, v1.w, h67, l67);
            int kb = c8 >> 4, half = (c8 >> 3) & 1;
            *(uint4*)(A + rowaddr(r, kb * 4 + half))     = make_uint4(h01, h23, h45, h67);
            *(uint4*)(A + rowaddr(r, kb * 4 + 2 + half)) = make_uint4(l01, l23, l45, l67);
        }
        // ---- stage ext: kb 4..5 ----
        for (int idx = tid; idx < TM * 4; idx += 256) {
            int r = idx >> 2, c8 = (idx & 3) << 3;
            int e = base + r;
            float4 v0, v1;
            if (e < n_edges) {
                v0 = *(const float4*)(ext + (size_t)e * EXT + c8);
                v1 = *(const float4*)(ext + (size_t)e * EXT + c8 + 4);
            } else {
                v0 = v1 = make_float4(0.f, 0.f, 0.f, 0.f);
            }
            unsigned h01, l01, h23, l23, h45, l45, h67, l67;
            split2(v0.x, v0.y, h01, l01);
            split2(v0.z, v0.w, h23, l23);
            split2(v1.x, v1.y, h45, l45);
            split2(v1.z, v1.w, h67, l67);
            int kb = 4 + (c8 >> 4), half = (c8 >> 3) & 1;
            *(uint4*)(A + rowaddr(r, kb * 4 + half))     = make_uint4(h01, h23, h45, h67);
            *(uint4*)(A + rowaddr(r, kb * 4 + 2 + half)) = make_uint4(l01, l23, l45, l67);
        }
        if (tid < TM) {
            int e = base + tid;
            srcs[tid] = (e < n_edges) ? src[e] : 0;
            dsts[tid] = (e < n_edges) ? dst[e] : 0;
        }
        __syncthreads();

        // ---- 8 m-tiles: per kb ldmatrix hi+lo, 3 MMAs ----
        float acc[8][4];
        #pragma unroll
        for (int mt = 0; mt < 8; mt++) {
            acc[mt][0] = acc[mt][1] = acc[mt][2] = acc[mt][3] = 0.f;
            int rr = mt * 16 + rbase;
            #pragma unroll
            for (int kb = 0; kb < 6; kb++) {
                uint4 Ah, Al;
                ldm4(Ah, smb + rowaddr(rr, kb * 4 + ubase));
                ldm4(Al, smb + rowaddr(rr, kb * 4 + 2 + ubase));
                mma16816(acc[mt], Ah, bh0[kb], bh1[kb]);   // hi*hi
                mma16816(acc[mt], Ah, bl0[kb], bl1[kb]);   // hi*lo
                mma16816(acc[mt], Al, bh0[kb], bh1[kb]);   // lo*hi
            }
        }

        // ---- epilogue: relu(acc + P[src] + Q[dst]) ----
        const int c = n0 + lc * 2;
        #pragma unroll
        for (int mt = 0; mt < 8; mt++) {
            int r1 = mt * 16 + lr, r2 = r1 + 8;
            int e1 = base + r1, e2 = base + r2;
            if (e1 < n_edges) {
                float2 p = *(const float2*)(g_P + (size_t)srcs[r1] * HID + c);
                float2 q = *(const float2*)(g_Q + (size_t)dsts[r1] * HID + c);
                float2 o;
                o.x = fmaxf(acc[mt][0] + p.x + q.x, 0.f);
                o.y = fmaxf(acc[mt][1] + p.y + q.y, 0.f);
                *(float2*)(out + (size_t)e1 * HID + c) = o;
            }
            if (e2 < n_edges) {
                float2 p = *(const float2*)(g_P + (size_t)srcs[r2] * HID + c);
                float2 q = *(const float2*)(g_Q + (size_t)dsts[r2] * HID + c);
                float2 o;
                o.x = fmaxf(acc[mt][2] + p.x + q.x, 0.f);
                o.y = fmaxf(acc[mt][3] + p.y + q.y, 0.f);
                *(float2*)(out + (size_t)e2 * HID + c) = o;
            }
        }
    }
}

// ---------------------------------------------------------------------------
extern "C" void kernel_launch(void* const* d_in, const int* in_sizes, int n_in,
                              void* d_out, int out_size)
{
    const float* h   = (const float*)d_in[0];
    const float* e_h = (const float*)d_in[1];
    const float* ext = (const float*)d_in[2];
    const float* W1  = (const float*)d_in[3];
    const float* b1  = (const float*)d_in[4];
    const float* W2  = (const float*)d_in[5];
    const float* b2  = (const float*)d_in[6];
    const int*   src = (const int*)d_in[7];
    const int*   dst = (const int*)d_in[8];
    float* out = (float*)d_out;

    int n_nodes = in_sizes[0] / HID;
    int n_edges = in_sizes[7];

    cudaFuncSetAttribute(node_pre, cudaFuncAttributeMaxDynamicSharedMemorySize,
                         NODE_SMEM_BYTES);
    cudaFuncSetAttribute(edge_kernel, cudaFuncAttributeMaxDynamicSharedMemorySize,
                         EDGE_SMEM_BYTES);

    combo_kernel<<<49, 256>>>(W1, b1, W2, b2);
    build_B<<<12, 256>>>(W2);

    int node_tiles = (n_nodes + TN - 1) / TN;
    int grid1 = node_tiles < 592 ? node_tiles : 592;
    node_pre<<<grid1, 256, NODE_SMEM_BYTES>>>(h, n_nodes);

    int edge_tiles = (n_edges + TM - 1) / TM;
    int grid2 = edge_tiles < 592 ? edge_tiles : 592;
    edge_kernel<<<grid2, 256, EDGE_SMEM_BYTES>>>(e_h, ext, src, dst, out, n_edges);
}

// round 11
// speedup vs baseline: 1.1400x; 1.1400x over previous
#include <cuda_runtime.h>
#include <cstdint>

#define HID 64
#define EXT 32
#define TN 64
#define TM 128          // edges per tile
#define MAX_NODES 50000

// ---------------------------------------------------------------------------
// Globals
// ---------------------------------------------------------------------------
__device__ float g_P[MAX_NODES * HID];        // h @ (W1a@W2a)
__device__ float g_Q[MAX_NODES * HID];        // h @ (W1c@W2a) + b12 (bias baked in)
__device__ float g_W12[HID * HID];            // W1b @ W2a (fp32)
__device__ float g_Wa2[HID * HID];
__device__ float g_Wc2[HID * HID];
__device__ float g_b12[HID];                  // b1 @ W2a + b2
// Split bf16 weights, packed as bf16x2 per k-pair: g_Bp[kp][n], kp = k/2.
// kp [0:32)=W12_hi [32:64)=W12_lo [64:80)=W2b_hi [80:96)=W2b_lo
__device__ unsigned g_Bp[96 * 64];

typedef unsigned long long u64;

// Single extern shared declaration for all kernels
extern __shared__ __align__(16) unsigned char smraw[];

// ---------------------------------------------------------------------------
// Helpers
// ---------------------------------------------------------------------------
__device__ __forceinline__ u64 pk2(float x, float y) {
    u64 r; asm("mov.b64 %0,{%1,%2};" : "=l"(r) : "f"(x), "f"(y)); return r;
}
__device__ __forceinline__ float2 up2(u64 v) {
    float2 f; asm("mov.b64 {%0,%1},%2;" : "=f"(f.x), "=f"(f.y) : "l"(v)); return f;
}
__device__ __forceinline__ void ffma2(u64& d, u64 a, u64 b) {
    asm("fma.rn.f32x2 %0,%1,%2,%0;" : "+l"(d) : "l"(a), "l"(b));
}
// bf16 hi/lo split of two floats, packed as bf16x2 words (x0 -> low half)
__device__ __forceinline__ void split2(float x0, float x1, unsigned& hi, unsigned& lo) {
    unsigned h;
    asm("cvt.rn.bf16x2.f32 %0, %1, %2;" : "=r"(h) : "f"(x1), "f"(x0));
    float h0 = __uint_as_float(h << 16);
    float h1 = __uint_as_float(h & 0xFFFF0000u);
    float l0 = x0 - h0, l1 = x1 - h1;
    unsigned l;
    asm("cvt.rn.bf16x2.f32 %0, %1, %2;" : "=r"(l) : "f"(l1), "f"(l0));
    hi = h; lo = l;
}
__device__ __forceinline__ void mma16816(float* c, uint4 a, unsigned b0, unsigned b1) {
    asm volatile(
        "mma.sync.aligned.m16n8k16.row.col.f32.bf16.bf16.f32 "
        "{%0,%1,%2,%3},{%4,%5,%6,%7},{%8,%9},{%0,%1,%2,%3};"
        : "+f"(c[0]), "+f"(c[1]), "+f"(c[2]), "+f"(c[3])
        : "r"(a.x), "r"(a.y), "r"(a.z), "r"(a.w), "r"(b0), "r"(b1));
}

// ---------------------------------------------------------------------------
// Kernel 0a: fold W2a into W1 parts + bias.  grid 49 x 256
// ---------------------------------------------------------------------------
__global__ __launch_bounds__(256) void combo_kernel(
    const float* __restrict__ W1, const float* __restrict__ b1,
    const float* __restrict__ W2, const float* __restrict__ b2)
{
    __shared__ float W2s[HID * HID];
    __shared__ float rW[256];
    for (int i = threadIdx.x; i < HID * HID; i += 256) W2s[i] = W2[i];

    int b = blockIdx.x;
    if (b < 48) {
        int mat = b >> 4, rb = b & 15;
        rW[threadIdx.x] = W1[(size_t)mat * HID * HID + rb * 256 + threadIdx.x];
        __syncthreads();
        int lr = threadIdx.x >> 6, col = threadIdx.x & 63;
        float acc = 0.f;
        #pragma unroll 8
        for (int k = 0; k < HID; k++)
            acc = fmaf(rW[lr * HID + k], W2s[k * HID + col], acc);
        float* dstW = (mat == 0) ? g_Wa2 : (mat == 1) ? g_W12 : g_Wc2;
        dstW[(rb * 4 + lr) * HID + col] = acc;
    } else {
        __syncthreads();
        if (threadIdx.x < HID) {
            float acc = b2[threadIdx.x];
            #pragma unroll 8
            for (int k = 0; k < HID; k++)
                acc = fmaf(b1[k], W2s[k * HID + threadIdx.x], acc);
            g_b12[threadIdx.x] = acc;
        }
    }
}

// ---------------------------------------------------------------------------
// Kernel 0b: build split bf16x2 weight blob.  grid 12 x 256
// ---------------------------------------------------------------------------
__global__ __launch_bounds__(256) void build_B(const float* __restrict__ W2)
{
    int idx = blockIdx.x * 256 + threadIdx.x;
    if (idx < 48 * 64) {
        int kp = idx >> 6, n = idx & 63;
        float x0, x1;
        int hi_kp, lo_kp;
        if (kp < 32) {
            x0 = g_W12[(2 * kp) * HID + n];
            x1 = g_W12[(2 * kp + 1) * HID + n];
            hi_kp = kp; lo_kp = 32 + kp;
        } else {
            int ks = kp - 32;
            x0 = W2[(size_t)(HID + 2 * ks) * HID + n];
            x1 = W2[(size_t)(HID + 2 * ks + 1) * HID + n];
            hi_kp = 64 + ks; lo_kp = 80 + ks;
        }
        unsigned hi, lo;
        split2(x0, x1, hi, lo);
        g_Bp[hi_kp * 64 + n] = hi;
        g_Bp[lo_kp * 64 + n] = lo;
    }
}

// ---------------------------------------------------------------------------
// Kernel 1: per-node  P = h @ Wa2 ; Q = h @ Wc2 + b12   (FFMA2)
// ---------------------------------------------------------------------------
#define NODE_SMEM_BYTES ((4096 + 4096 + HID * TN) * 4)

__global__ __launch_bounds__(256) void node_pre(const float* __restrict__ h,
                                                int n_nodes)
{
    float* sm  = (float*)smraw;
    float* Wa  = sm;
    float* Wc  = Wa + 4096;
    float* hst = Wc + 4096;

    for (int i = threadIdx.x; i < HID * HID; i += 256) {
        Wa[i] = g_Wa2[i];
        Wc[i] = g_Wc2[i];
    }

    const int tx = threadIdx.x & 15;
    const int ty = threadIdx.x >> 4;
    const int j0 = tx * 4;
    const int r0 = ty * 4;
    const int ntiles = (n_nodes + TN - 1) / TN;

    float4 bv = *(const float4*)(g_b12 + j0);
    u64 qb0 = pk2(bv.x, bv.x), qb1 = pk2(bv.y, bv.y),
        qb2 = pk2(bv.z, bv.z), qb3 = pk2(bv.w, bv.w);

    for (int tile = blockIdx.x; tile < ntiles; tile += gridDim.x) {
        const int base = tile * TN;
        __syncthreads();
        for (int idx = threadIdx.x; idx < (HID / 4) * TN; idx += 256) {
            int cq = idx >> 6;
            int r  = idx & (TN - 1);
            int node = base + r;
            float4 v = make_float4(0.f, 0.f, 0.f, 0.f);
            if (node < n_nodes) v = *(const float4*)(h + (size_t)node * HID + cq * 4);
            hst[(cq * 4 + 0) * TN + r] = v.x;
            hst[(cq * 4 + 1) * TN + r] = v.y;
            hst[(cq * 4 + 2) * TN + r] = v.z;
            hst[(cq * 4 + 3) * TN + r] = v.w;
        }
        __syncthreads();

        u64 aP[4][2], aQ[4][2];
        #pragma unroll
        for (int j = 0; j < 4; j++) aP[j][0] = aP[j][1] = 0ULL;
        aQ[0][0] = aQ[0][1] = qb0;
        aQ[1][0] = aQ[1][1] = qb1;
        aQ[2][0] = aQ[2][1] = qb2;
        aQ[3][0] = aQ[3][1] = qb3;

        #pragma unroll 4
        for (int k = 0; k < HID; k++) {
            ulonglong2 sv = *(const ulonglong2*)(hst + k * TN + r0);
            float4 wa = *(const float4*)(Wa + k * HID + j0);
            float4 wc = *(const float4*)(Wc + k * HID + j0);
            u64 a0 = pk2(wa.x, wa.x), a1 = pk2(wa.y, wa.y),
                a2 = pk2(wa.z, wa.z), a3 = pk2(wa.w, wa.w);
            u64 c0 = pk2(wc.x, wc.x), c1 = pk2(wc.y, wc.y),
                c2 = pk2(wc.z, wc.z), c3 = pk2(wc.w, wc.w);
            ffma2(aP[0][0], a0, sv.x); ffma2(aP[0][1], a0, sv.y);
            ffma2(aP[1][0], a1, sv.x); ffma2(aP[1][1], a1, sv.y);
            ffma2(aP[2][0], a2, sv.x); ffma2(aP[2][1], a2, sv.y);
            ffma2(aP[3][0], a3, sv.x); ffma2(aP[3][1], a3, sv.y);
            ffma2(aQ[0][0], c0, sv.x); ffma2(aQ[0][1], c0, sv.y);
            ffma2(aQ[1][0], c1, sv.x); ffma2(aQ[1][1], c1, sv.y);
            ffma2(aQ[2][0], c2, sv.x); ffma2(aQ[2][1], c2, sv.y);
            ffma2(aQ[3][0], c3, sv.x); ffma2(aQ[3][1], c3, sv.y);
        }
        #pragma unroll
        for (int r = 0; r < 4; r++) {
            int node = base + r0 + r;
            if (node < n_nodes) {
                float4 p, q; float2 c;
                c = up2(aP[0][r >> 1]); p.x = (r & 1) ? c.y : c.x;
                c = up2(aP[1][r >> 1]); p.y = (r & 1) ? c.y : c.x;
                c = up2(aP[2][r >> 1]); p.z = (r & 1) ? c.y : c.x;
                c = up2(aP[3][r >> 1]); p.w = (r & 1) ? c.y : c.x;
                c = up2(aQ[0][r >> 1]); q.x = (r & 1) ? c.y : c.x;
                c = up2(aQ[1][r >> 1]); q.y = (r & 1) ? c.y : c.x;
                c = up2(aQ[2][r >> 1]); q.z = (r & 1) ? c.y : c.x;
                c = up2(aQ[3][r >> 1]); q.w = (r & 1) ? c.y : c.x;
                *(float4*)(g_P + (size_t)node * HID + j0) = p;
                *(float4*)(g_Q + (size_t)node * HID + j0) = q;
            }
        }
    }
}

// ---------------------------------------------------------------------------
// Kernel 2: per-edge via mma.sync, fragment-linear A (R9 consumer) with
// fragment-direct STS.128 producer.
//   A kt blocks: 0-3 eh_hi | 4-7 eh_lo | 8-9 ext_hi | 10-11 ext_lo
//   Main B:  kt0-7 -> W12_hi, kt8-11 -> W2b_hi   (hi*hi + lo*hi)
//   Cross B: kt0-3 -> W12_lo, kt8-9 -> W2b_lo    (hi*lo, reusing A frags)
//   out = relu( sum + P[src] + Q[dst] )
// A layout: frag block (mt,kt) = 32 lanes x 16B; lane unit = regs a0..a3 of
// that lane's mma fragment: {(r,kp),(r+8,kp),(r,kp+4),(r+8,kp+4)}.
// ---------------------------------------------------------------------------
#define A_BYTES (8 * 12 * 32 * 16)      // 49152
#define OFF_SRC A_BYTES
#define OFF_DST (OFF_SRC + TM * 4)
#define EDGE_SMEM_BYTES (OFF_DST + TM * 4)

__global__ __launch_bounds__(256) void edge_kernel(
    const float* __restrict__ e_h,
    const float* __restrict__ ext,
    const int* __restrict__ src,
    const int* __restrict__ dst,
    float* __restrict__ out,
    int n_edges)
{
    unsigned char* A = smraw;
    int* srcs = (int*)(smraw + OFF_SRC);
    int* dsts = (int*)(smraw + OFF_DST);

    const int tid = threadIdx.x;
    const int w = tid >> 5, lane = tid & 31;
    const int n0 = w * 8;
    const int lr = lane >> 2;            // 0..7
    const int lc = lane & 3;             // 0..3

    // ---- B fragments (registers, live whole kernel) ----
    unsigned bm0[12], bm1[12];
    #pragma unroll
    for (int kt = 0; kt < 8; kt++) {               // A = eh_hi (0-3), eh_lo (4-7) -> W12_hi
        int kp = (kt & 3) * 8 + lc;
        bm0[kt] = g_Bp[kp * 64 + n0 + lr];
        bm1[kt] = g_Bp[(kp + 4) * 64 + n0 + lr];
    }
    #pragma unroll
    for (int kt = 8; kt < 12; kt++) {              // A = ext_hi (8-9), ext_lo (10-11) -> W2b_hi
        int kp = 64 + ((kt - 8) & 1) * 8 + lc;
        bm0[kt] = g_Bp[kp * 64 + n0 + lr];
        bm1[kt] = g_Bp[(kp + 4) * 64 + n0 + lr];
    }
    unsigned bc0[6], bc1[6];
    #pragma unroll
    for (int j = 0; j < 4; j++) {                  // W12_lo
        int kp = 32 + j * 8 + lc;
        bc0[j] = g_Bp[kp * 64 + n0 + lr];
        bc1[j] = g_Bp[(kp + 4) * 64 + n0 + lr];
    }
    #pragma unroll
    for (int j = 4; j < 6; j++) {                  // W2b_lo
        int kp = 80 + (j - 4) * 8 + lc;
        bc0[j] = g_Bp[kp * 64 + n0 + lr];
        bc1[j] = g_Bp[(kp + 4) * 64 + n0 + lr];
    }

    const int ntiles = (n_edges + TM - 1) / TM;

    for (int tile = blockIdx.x; tile < ntiles; tile += gridDim.x) {
        const int base = tile * TM;
        __syncthreads();   // previous tile fully consumed before A overwrite

        // ---- fragment-direct staging ----
        // item < 256: e_h, (mt 0..7, rq 0..7, kb 0..3), 16 cols, rows r0 & r0+8
        // item >= 256: ext, (mt 0..7, rq 0..7, kb 0..1)
        for (int idx = tid; idx < 384; idx += 256) {
            int mt, rq, kb, kt_hi, kt_lo;
            const float* sp; int strd;
            if (idx < 256) {
                mt = idx >> 5; rq = (idx >> 2) & 7; kb = idx & 3;
                sp = e_h; strd = HID;
                kt_hi = kb; kt_lo = 4 + kb;
            } else {
                int it = idx - 256;
                mt = it >> 4; rq = (it >> 1) & 7; kb = it & 1;
                sp = ext; strd = EXT;
                kt_hi = 8 + kb; kt_lo = 10 + kb;
            }
            const int c0 = kb * 16;
            const int r0 = mt * 16 + rq;
            const int e0 = base + r0, e1 = e0 + 8;

            float4 x0a, x0b, x0c, x0d, x1a, x1b, x1c, x1d;
            if (e0 < n_edges) {
                const float* p0 = sp + (size_t)e0 * strd + c0;
                x0a = *(const float4*)(p0 + 0);
                x0b = *(const float4*)(p0 + 4);
                x0c = *(const float4*)(p0 + 8);
                x0d = *(const float4*)(p0 + 12);
            } else x0a = x0b = x0c = x0d = make_float4(0.f, 0.f, 0.f, 0.f);
            if (e1 < n_edges) {
                const float* p1 = sp + (size_t)e1 * strd + c0;
                x1a = *(const float4*)(p1 + 0);
                x1b = *(const float4*)(p1 + 4);
                x1c = *(const float4*)(p1 + 8);
                x1d = *(const float4*)(p1 + 12);
            } else x1a = x1b = x1c = x1d = make_float4(0.f, 0.f, 0.f, 0.f);

            unsigned h0[8], l0[8], h1[8], l1[8];
            split2(x0a.x, x0a.y, h0[0], l0[0]);
            split2(x0a.z, x0a.w, h0[1], l0[1]);
            split2(x0b.x, x0b.y, h0[2], l0[2]);
            split2(x0b.z, x0b.w, h0[3], l0[3]);
            split2(x0c.x, x0c.y, h0[4], l0[4]);
            split2(x0c.z, x0c.w, h0[5], l0[5]);
            split2(x0d.x, x0d.y, h0[6], l0[6]);
            split2(x0d.z, x0d.w, h0[7], l0[7]);
            split2(x1a.x, x1a.y, h1[0], l1[0]);
            split2(x1a.z, x1a.w, h1[1], l1[1]);
            split2(x1b.x, x1b.y, h1[2], l1[2]);
            split2(x1b.z, x1b.w, h1[3], l1[3]);
            split2(x1c.x, x1c.y, h1[4], l1[4]);
            split2(x1c.z, x1c.w, h1[5], l1[5]);
            split2(x1d.x, x1d.y, h1[6], l1[6]);
            split2(x1d.z, x1d.w, h1[7], l1[7]);

            uint4* dhi = (uint4*)A + (mt * 12 + kt_hi) * 32 + rq * 4;
            uint4* dlo = (uint4*)A + (mt * 12 + kt_lo) * 32 + rq * 4;
            #pragma unroll
            for (int m = 0; m < 4; m++) {
                int mm = (m + rq) & 3;   // rotate store order: 4-way -> 2-way bank conflict
                dhi[mm] = make_uint4(h0[mm], h1[mm], h0[mm + 4], h1[mm + 4]);
                dlo[mm] = make_uint4(l0[mm], l1[mm], l0[mm + 4], l1[mm + 4]);
            }
        }
        if (tid < TM) {
            int e = base + tid;
            srcs[tid] = (e < n_edges) ? src[e] : 0;
            dsts[tid] = (e < n_edges) ? dst[e] : 0;
        }
        __syncthreads();

        // ---- 8 m-tiles: 12 main + 6 cross MMAs each (A frags via LDS.128) ----
        float acc[8][4];
        #pragma unroll
        for (int mt = 0; mt < 8; mt++) {
            acc[mt][0] = acc[mt][1] = acc[mt][2] = acc[mt][3] = 0.f;
            const uint4* Ab = (const uint4*)(A) + (mt * 12) * 32 + lane;
            #pragma unroll
            for (int kt = 0; kt < 12; kt++) {
                uint4 a = Ab[kt * 32];
                mma16816(acc[mt], a, bm0[kt], bm1[kt]);
                if (kt < 4)
                    mma16816(acc[mt], a, bc0[kt], bc1[kt]);          // eh_hi x W12_lo
                else if (kt == 8 || kt == 9)
                    mma16816(acc[mt], a, bc0[kt - 4], bc1[kt - 4]);  // ext_hi x W2b_lo
            }
        }

        // ---- epilogue: relu(acc + P[src] + Q[dst]) ----
        const int c = n0 + lc * 2;
        #pragma unroll
        for (int mt = 0; mt < 8; mt++) {
            int r1 = mt * 16 + lr, r2 = r1 + 8;
            int e1 = base + r1, e2 = base + r2;
            if (e1 < n_edges) {
                float2 p = *(const float2*)(g_P + (size_t)srcs[r1] * HID + c);
                float2 q = *(const float2*)(g_Q + (size_t)dsts[r1] * HID + c);
                float2 o;
                o.x = fmaxf(acc[mt][0] + p.x + q.x, 0.f);
                o.y = fmaxf(acc[mt][1] + p.y + q.y, 0.f);
                *(float2*)(out + (size_t)e1 * HID + c) = o;
            }
            if (e2 < n_edges) {
                float2 p = *(const float2*)(g_P + (size_t)srcs[r2] * HID + c);
                float2 q = *(const float2*)(g_Q + (size_t)dsts[r2] * HID + c);
                float2 o;
                o.x = fmaxf(acc[mt][2] + p.x + q.x, 0.f);
                o.y = fmaxf(acc[mt][3] + p.y + q.y, 0.f);
                *(float2*)(out + (size_t)e2 * HID + c) = o;
            }
        }
    }
}

// ---------------------------------------------------------------------------
extern "C" void kernel_launch(void* const* d_in, const int* in_sizes, int n_in,
                              void* d_out, int out_size)
{
    const float* h   = (const float*)d_in[0];
    const float* e_h = (const float*)d_in[1];
    const float* ext = (const float*)d_in[2];
    const float* W1  = (const float*)d_in[3];
    const float* b1  = (const float*)d_in[4];
    const float* W2  = (const float*)d_in[5];
    const float* b2  = (const float*)d_in[6];
    const int*   src = (const int*)d_in[7];
    const int*   dst = (const int*)d_in[8];
    float* out = (float*)d_out;

    int n_nodes = in_sizes[0] / HID;
    int n_edges = in_sizes[7];

    cudaFuncSetAttribute(node_pre, cudaFuncAttributeMaxDynamicSharedMemorySize,
                         NODE_SMEM_BYTES);
    cudaFuncSetAttribute(edge_kernel, cudaFuncAttributeMaxDynamicSharedMemorySize,
                         EDGE_SMEM_BYTES);

    combo_kernel<<<49, 256>>>(W1, b1, W2, b2);
    build_B<<<12, 256>>>(W2);

    int node_tiles = (n_nodes + TN - 1) / TN;
    int grid1 = node_tiles < 592 ? node_tiles : 592;
    node_pre<<<grid1, 256, NODE_SMEM_BYTES>>>(h, n_nodes);

    int edge_tiles = (n_edges + TM - 1) / TM;
    int grid2 = edge_tiles < 444 ? edge_tiles : 444;
    edge_kernel<<<grid2, 256, EDGE_SMEM_BYTES>>>(e_h, ext, src, dst, out, n_edges);
}